// round 3
// baseline (speedup 1.0000x reference)
#include <cuda_runtime.h>
#include <cuda_bf16.h>

#define NN 100000
#define NE 1600000
#define NG 512
#define HID 64
#define NCLS 100
#define IDOFF 1500

// ---------------- device scratch ----------------
__device__ float g_h[NN * HID];        // layer input h (post-BN)
__device__ float g_x[NN * HID];        // (1+eps)*h + agg  (MLP input / RED target)
__device__ float g_y[NN * HID];        // MLP output (pre-BN)
__device__ float g_stats[3 * 2 * HID]; // per layer: sum[64], sumsq[64]
__device__ float g_pooled[NG * 3 * HID];

// ---------------- helpers ----------------
__device__ __forceinline__ unsigned f2tf(float f) {
    unsigned u;
    asm("cvt.rna.tf32.f32 %0, %1;" : "=r"(u) : "f"(f));
    return u;
}

__device__ __forceinline__ void mma8(float c[4], unsigned a0, unsigned a1,
                                     unsigned a2, unsigned a3,
                                     unsigned b0, unsigned b1) {
    asm volatile(
        "mma.sync.aligned.m16n8k8.row.col.f32.tf32.tf32.f32 "
        "{%0,%1,%2,%3}, {%4,%5,%6,%7}, {%8,%9}, {%0,%1,%2,%3};\n"
        : "+f"(c[0]), "+f"(c[1]), "+f"(c[2]), "+f"(c[3])
        : "r"(a0), "r"(a1), "r"(a2), "r"(a3), "r"(b0), "r"(b1));
}

// ---------------- kernels ----------------

__global__ void k_zero() {
    int t = blockIdx.x * blockDim.x + threadIdx.x;
    int stride = gridDim.x * blockDim.x;
    for (int i = t; i < NG * 3 * HID; i += stride) g_pooled[i] = 0.f;
    for (int i = t; i < 3 * 2 * HID; i += stride) g_stats[i] = 0.f;
}

// h = emb[node_ids + IDOFF]; x = (1+eps[0]) * h
__global__ void k_gather(const int* __restrict__ ids,
                         const float* __restrict__ emb,
                         const float* __restrict__ eps) {
    int t = blockIdx.x * blockDim.x + threadIdx.x;
    if (t >= NN * 16) return;
    int row = t >> 4, q = t & 15;
    int id = ids[row] + IDOFF;
    float s = 1.0f + __ldg(&eps[0]);
    float4 v = *(const float4*)(emb + (size_t)id * HID + q * 4);
    *(float4*)(g_h + (size_t)row * HID + q * 4) = v;
    float4 w = make_float4(v.x * s, v.y * s, v.z * s, v.w * s);
    *(float4*)(g_x + (size_t)row * HID + q * 4) = w;
}

// x[dst] += h[src]  (8 lanes / edge, 2x float4 vector RED per lane)
__global__ void k_edge(const int* __restrict__ src,
                       const int* __restrict__ dst) {
    int t = blockIdx.x * blockDim.x + threadIdx.x;
    if (t >= NE * 8) return;
    int e = t >> 3, q = t & 7;
    int s = __ldg(&src[e]);
    int d = __ldg(&dst[e]);
    const float4* ph = (const float4*)(g_h + (size_t)s * HID + q * 8);
    float4 v0 = __ldg(ph);
    float4 v1 = __ldg(ph + 1);
    float* p = g_x + (size_t)d * HID + q * 8;
    asm volatile("red.global.add.v4.f32 [%0], {%1,%2,%3,%4};"
                 :: "l"(p), "f"(v0.x), "f"(v0.y), "f"(v0.z), "f"(v0.w)
                 : "memory");
    asm volatile("red.global.add.v4.f32 [%0], {%1,%2,%3,%4};"
                 :: "l"(p + 4), "f"(v1.x), "f"(v1.y), "f"(v1.z), "f"(v1.w)
                 : "memory");
}

// Fused 3x (Linear 64x64 + ReLU) per GIN layer, 3xTF32 split mma, + BN stats.
#define MROWS 128
#define XS 76
#define WSTR 72
#define MLP_SMEM ((2 * MROWS * XS + 2 * HID * WSTR + HID + 2 * HID) * 4)

__global__ __launch_bounds__(256, 2)
void k_mlp(const float* __restrict__ Wall, const float* __restrict__ ball, int l) {
    extern __shared__ float sm[];
    float* Xbuf0 = sm;
    float* Xbuf1 = sm + MROWS * XS;
    unsigned* Whi = (unsigned*)(sm + 2 * MROWS * XS);
    unsigned* Wlo = Whi + HID * WSTR;
    float* Bsm = (float*)(Wlo + HID * WSTR);
    float* bstat = Bsm + HID;

    const int t = threadIdx.x;
    const int warp = t >> 5, lane = t & 31;
    const int g = lane >> 2, tg = lane & 3;
    const int row0 = blockIdx.x * MROWS;
    const int wrow = warp * 16;

    if (t < 2 * HID) bstat[t] = 0.f;

    for (int i = t; i < MROWS * 16; i += 256) {
        int r = i >> 4, q = i & 15;
        float4 v = make_float4(0.f, 0.f, 0.f, 0.f);
        int gr = row0 + r;
        if (gr < NN) v = *(const float4*)(g_x + (size_t)gr * HID + q * 4);
        float* p = Xbuf0 + r * XS + q * 4;
        p[0] = v.x; p[1] = v.y; p[2] = v.z; p[3] = v.w;
    }

    float* cur = Xbuf0;
    float* nxt = Xbuf1;

    for (int m = 0; m < 3; m++) {
        __syncthreads();
        const float* W = Wall + (size_t)(l * 3 + m) * HID * HID;
        for (int i = t; i < HID * 16; i += 256) {
            int k = i >> 4, q = i & 15;
            float4 w = *(const float4*)(W + (size_t)k * HID + q * 4);
            unsigned h0 = f2tf(w.x), h1 = f2tf(w.y), h2 = f2tf(w.z), h3 = f2tf(w.w);
            unsigned* ph = Whi + k * WSTR + q * 4;
            ph[0] = h0; ph[1] = h1; ph[2] = h2; ph[3] = h3;
            unsigned* pl = Wlo + k * WSTR + q * 4;
            pl[0] = f2tf(w.x - __uint_as_float(h0));
            pl[1] = f2tf(w.y - __uint_as_float(h1));
            pl[2] = f2tf(w.z - __uint_as_float(h2));
            pl[3] = f2tf(w.w - __uint_as_float(h3));
        }
        if (t < HID) Bsm[t] = ball[(l * 3 + m) * HID + t];
        __syncthreads();

        float acc[8][4];
        #pragma unroll
        for (int n = 0; n < 8; n++) {
            acc[n][0] = 0.f; acc[n][1] = 0.f; acc[n][2] = 0.f; acc[n][3] = 0.f;
        }

        #pragma unroll
        for (int k0 = 0; k0 < 8; k0++) {
            int kk = k0 * 8;
            float a0f = cur[(wrow + g) * XS + kk + tg];
            float a1f = cur[(wrow + g + 8) * XS + kk + tg];
            float a2f = cur[(wrow + g) * XS + kk + tg + 4];
            float a3f = cur[(wrow + g + 8) * XS + kk + tg + 4];
            unsigned a0h = f2tf(a0f), a1h = f2tf(a1f);
            unsigned a2h = f2tf(a2f), a3h = f2tf(a3f);
            unsigned a0l = f2tf(a0f - __uint_as_float(a0h));
            unsigned a1l = f2tf(a1f - __uint_as_float(a1h));
            unsigned a2l = f2tf(a2f - __uint_as_float(a2h));
            unsigned a3l = f2tf(a3f - __uint_as_float(a3h));
            #pragma unroll
            for (int n = 0; n < 8; n++) {
                unsigned b0h = Whi[(kk + tg) * WSTR + n * 8 + g];
                unsigned b1h = Whi[(kk + tg + 4) * WSTR + n * 8 + g];
                unsigned b0l = Wlo[(kk + tg) * WSTR + n * 8 + g];
                unsigned b1l = Wlo[(kk + tg + 4) * WSTR + n * 8 + g];
                mma8(acc[n], a0h, a1h, a2h, a3h, b0l, b1l);
                mma8(acc[n], a0l, a1l, a2l, a3l, b0h, b1h);
                mma8(acc[n], a0h, a1h, a2h, a3h, b0h, b1h);
            }
        }

        if (m < 2) {
            #pragma unroll
            for (int n = 0; n < 8; n++) {
                int c = n * 8 + 2 * tg;
                float b0f = Bsm[c], b1f = Bsm[c + 1];
                float d0 = fmaxf(acc[n][0] + b0f, 0.f);
                float d1 = fmaxf(acc[n][1] + b1f, 0.f);
                float d2 = fmaxf(acc[n][2] + b0f, 0.f);
                float d3 = fmaxf(acc[n][3] + b1f, 0.f);
                float* p0 = nxt + (wrow + g) * XS + c;
                p0[0] = d0; p0[1] = d1;
                float* p1 = nxt + (wrow + g + 8) * XS + c;
                p1[0] = d2; p1[1] = d3;
            }
            float* tmp = cur; cur = nxt; nxt = tmp;
        } else {
            int r0v = row0 + wrow + g;
            int r1v = r0v + 8;
            bool v0 = r0v < NN, v1 = r1v < NN;
            #pragma unroll
            for (int n = 0; n < 8; n++) {
                int c = n * 8 + 2 * tg;
                float b0f = Bsm[c], b1f = Bsm[c + 1];
                float d0 = fmaxf(acc[n][0] + b0f, 0.f);
                float d1 = fmaxf(acc[n][1] + b1f, 0.f);
                float d2 = fmaxf(acc[n][2] + b0f, 0.f);
                float d3 = fmaxf(acc[n][3] + b1f, 0.f);
                if (v0) *(float2*)(g_y + (size_t)r0v * HID + c) = make_float2(d0, d1);
                if (v1) *(float2*)(g_y + (size_t)r1v * HID + c) = make_float2(d2, d3);
                float s0 = (v0 ? d0 : 0.f) + (v1 ? d2 : 0.f);
                float s1 = (v0 ? d1 : 0.f) + (v1 ? d3 : 0.f);
                float q0 = (v0 ? d0 * d0 : 0.f) + (v1 ? d2 * d2 : 0.f);
                float q1 = (v0 ? d1 * d1 : 0.f) + (v1 ? d3 * d3 : 0.f);
                #pragma unroll
                for (int off = 4; off < 32; off <<= 1) {
                    s0 += __shfl_xor_sync(0xffffffffu, s0, off);
                    s1 += __shfl_xor_sync(0xffffffffu, s1, off);
                    q0 += __shfl_xor_sync(0xffffffffu, q0, off);
                    q1 += __shfl_xor_sync(0xffffffffu, q1, off);
                }
                if (g == 0) {
                    atomicAdd(&bstat[c], s0);
                    atomicAdd(&bstat[c + 1], s1);
                    atomicAdd(&bstat[HID + c], q0);
                    atomicAdd(&bstat[HID + c + 1], q1);
                }
            }
        }
    }
    __syncthreads();
    if (t < 2 * HID) atomicAdd(&g_stats[l * 2 * HID + t], bstat[t]);
}

// BN apply + per-graph pooling + next-layer g_x pre-init.
// 256 threads = 4 sub-blocks of 64 channels, each sub handles 64 rows.
__global__ void k_bnpool(const int* __restrict__ graph_ids,
                         const float* __restrict__ gamma,
                         const float* __restrict__ beta,
                         const float* __restrict__ eps, int l) {
    __shared__ int gid[256];
    int t = threadIdx.x;
    int c = t & 63, sub = t >> 6;
    int base = blockIdx.x * 256;
    int nrow_blk = NN - base; if (nrow_blk > 256) nrow_blk = 256;
    if (t < nrow_blk) gid[t] = graph_ids[base + t];
    __syncthreads();

    float sum = g_stats[l * 2 * HID + c];
    float sq = g_stats[l * 2 * HID + HID + c];
    const float invN = 1.0f / (float)NN;
    float mean = sum * invN;
    float var = sq * invN - mean * mean;
    float inv = rsqrtf(var + 1e-5f);
    float sc = __ldg(&gamma[l * HID + c]) * inv;
    float sh = __ldg(&beta[l * HID + c]) - mean * sc;

    int r0 = sub * 64;
    int nr = nrow_blk - r0; if (nr > 64) nr = 64;
    if (nr <= 0) return;

    float s2 = (l < 2) ? 1.0f + __ldg(&eps[l + 1]) : 0.f;

    float run = 0.f;
    int gcur = gid[r0];
    for (int r = 0; r < nr; r++) {
        int gg = gid[r0 + r];
        if (gg != gcur) {
            atomicAdd(&g_pooled[(size_t)gcur * (3 * HID) + l * HID + c], run);
            run = 0.f;
            gcur = gg;
        }
        size_t off = (size_t)(base + r0 + r) * HID + c;
        float v = g_y[off] * sc + sh;
        if (l < 2) {
            g_h[off] = v;
            g_x[off] = s2 * v;
        }
        run += v;
    }
    atomicAdd(&g_pooled[(size_t)gcur * (3 * HID) + l * HID + c], run);
}

// out[g] = pooled[g] @ W_out + b_out
__global__ void k_out(const float* __restrict__ Wo,
                      const float* __restrict__ bo,
                      float* __restrict__ out) {
    __shared__ float p[3 * HID];
    int gr = blockIdx.x;
    int t = threadIdx.x;
    for (int i = t; i < 3 * HID; i += blockDim.x)
        p[i] = g_pooled[(size_t)gr * (3 * HID) + i];
    __syncthreads();
    if (t < NCLS) {
        float a = __ldg(&bo[t]);
        #pragma unroll 8
        for (int k = 0; k < 3 * HID; k++) a += p[k] * Wo[(size_t)k * NCLS + t];
        out[(size_t)gr * NCLS + t] = a;
    }
}

// ---------------- launch ----------------
extern "C" void kernel_launch(void* const* d_in, const int* in_sizes, int n_in,
                              void* d_out, int out_size) {
    const int* node_ids = (const int*)d_in[0];
    const int* edge_src = (const int*)d_in[1];
    const int* edge_dst = (const int*)d_in[2];
    const int* graph_ids = (const int*)d_in[3];
    const float* emb = (const float*)d_in[4];
    const float* Ws = (const float*)d_in[5];
    const float* bs = (const float*)d_in[6];
    const float* gamma = (const float*)d_in[7];
    const float* beta = (const float*)d_in[8];
    const float* eps = (const float*)d_in[9];
    const float* Wo = (const float*)d_in[10];
    const float* bo = (const float*)d_in[11];
    float* out = (float*)d_out;

    cudaFuncSetAttribute(k_mlp, cudaFuncAttributeMaxDynamicSharedMemorySize,
                         MLP_SMEM);

    k_zero<<<256, 256>>>();
    k_gather<<<(NN * 16 + 255) / 256, 256>>>(node_ids, emb, eps);

    for (int l = 0; l < 3; l++) {
        k_edge<<<(NE * 8 + 255) / 256, 256>>>(edge_src, edge_dst);
        k_mlp<<<(NN + MROWS - 1) / MROWS, 256, MLP_SMEM>>>(Ws, bs, l);
        k_bnpool<<<(NN + 255) / 256, 256>>>(graph_ids, gamma, beta, eps, l);
    }

    k_out<<<NG, 128>>>(Wo, bo, out);
}

// round 4
// speedup vs baseline: 1.0642x; 1.0642x over previous
#include <cuda_runtime.h>
#include <cuda_bf16.h>

#define NN 100000
#define NE 1600000
#define NG 512
#define HID 64
#define NCLS 100
#define IDOFF 1500

// ---------------- device scratch ----------------
__device__ float g_h[NN * HID];        // layer input h (post-BN)
__device__ float g_x[NN * HID];        // (1+eps)*h + agg  (MLP input)
__device__ float g_y[NN * HID];        // MLP output (pre-BN)
__device__ float g_stats[3 * 2 * HID];
__device__ float g_pooled[NG * 3 * HID];
// CSR build (per-launch, graph static within launch)
__device__ int g_deg[NN];
__device__ int g_off[NN + 1];
__device__ int g_cur[NN];
__device__ int g_csr[NE];

// ---------------- helpers ----------------
__device__ __forceinline__ unsigned f2tf(float f) {
    unsigned u;
    asm("cvt.rna.tf32.f32 %0, %1;" : "=r"(u) : "f"(f));
    return u;
}

__device__ __forceinline__ void mma8(float c[4], unsigned a0, unsigned a1,
                                     unsigned a2, unsigned a3,
                                     unsigned b0, unsigned b1) {
    asm volatile(
        "mma.sync.aligned.m16n8k8.row.col.f32.tf32.tf32.f32 "
        "{%0,%1,%2,%3}, {%4,%5,%6,%7}, {%8,%9}, {%0,%1,%2,%3};\n"
        : "+f"(c[0]), "+f"(c[1]), "+f"(c[2]), "+f"(c[3])
        : "r"(a0), "r"(a1), "r"(a2), "r"(a3), "r"(b0), "r"(b1));
}

// ---------------- kernels ----------------

// zero pooled + stats + degree histogram
__global__ void k_zero() {
    int t = blockIdx.x * blockDim.x + threadIdx.x;
    int stride = gridDim.x * blockDim.x;
    for (int i = t; i < NG * 3 * HID; i += stride) g_pooled[i] = 0.f;
    for (int i = t; i < 3 * 2 * HID; i += stride) g_stats[i] = 0.f;
    for (int i = t; i < NN; i += stride) g_deg[i] = 0;
}

__global__ void k_hist(const int* __restrict__ dst) {
    int e = blockIdx.x * blockDim.x + threadIdx.x;
    if (e < NE) atomicAdd(&g_deg[__ldg(&dst[e])], 1);
}

// single-block exclusive scan of g_deg -> g_off, g_cur
__global__ void k_scan() {
    __shared__ int ssum[1024];
    int t = threadIdx.x;
    const int CH = (NN + 1023) / 1024;
    int beg = t * CH;
    int end = beg + CH; if (end > NN) end = NN;
    int s = 0;
    for (int i = beg; i < end; i++) s += g_deg[i];
    ssum[t] = s;
    __syncthreads();
    for (int off = 1; off < 1024; off <<= 1) {
        int v = (t >= off) ? ssum[t - off] : 0;
        __syncthreads();
        ssum[t] += v;
        __syncthreads();
    }
    int run = (t > 0) ? ssum[t - 1] : 0;
    for (int i = beg; i < end; i++) {
        int d = g_deg[i];
        g_off[i] = run;
        g_cur[i] = run;
        run += d;
    }
    if (t == 1023) g_off[NN] = run;
}

__global__ void k_scatter(const int* __restrict__ src,
                          const int* __restrict__ dst) {
    int e = blockIdx.x * blockDim.x + threadIdx.x;
    if (e >= NE) return;
    int d = __ldg(&dst[e]);
    int pos = atomicAdd(&g_cur[d], 1);
    g_csr[pos] = __ldg(&src[e]);
}

// h = emb[node_ids + IDOFF]
__global__ void k_gather(const int* __restrict__ ids,
                         const float* __restrict__ emb) {
    int t = blockIdx.x * blockDim.x + threadIdx.x;
    if (t >= NN * 16) return;
    int row = t >> 4, q = t & 15;
    int id = ids[row] + IDOFF;
    float4 v = *(const float4*)(emb + (size_t)id * HID + q * 4);
    *(float4*)(g_h + (size_t)row * HID + q * 4) = v;
}

// x[n] = (1+eps[l]) * h[n] + sum_{s in in-nbrs(n)} h[s]   (warp per node)
__global__ __launch_bounds__(256)
void k_agg(const float* __restrict__ eps, int l) {
    int wid = (blockIdx.x * blockDim.x + threadIdx.x) >> 5;
    if (wid >= NN) return;
    int lane = threadIdx.x & 31;
    int beg = __ldg(&g_off[wid]);
    int end = __ldg(&g_off[wid + 1]);
    float2 a0 = make_float2(0.f, 0.f);
    float2 a1 = make_float2(0.f, 0.f);
    int j = beg;
    for (; j + 1 < end; j += 2) {
        int s0 = __ldg(&g_csr[j]);
        int s1 = __ldg(&g_csr[j + 1]);
        float2 v0 = __ldg((const float2*)(g_h + (size_t)s0 * HID + lane * 2));
        float2 v1 = __ldg((const float2*)(g_h + (size_t)s1 * HID + lane * 2));
        a0.x += v0.x; a0.y += v0.y;
        a1.x += v1.x; a1.y += v1.y;
    }
    if (j < end) {
        int s0 = __ldg(&g_csr[j]);
        float2 v0 = __ldg((const float2*)(g_h + (size_t)s0 * HID + lane * 2));
        a0.x += v0.x; a0.y += v0.y;
    }
    float se = 1.0f + __ldg(&eps[l]);
    float2 hv = *(const float2*)(g_h + (size_t)wid * HID + lane * 2);
    float2 o = make_float2(se * hv.x + a0.x + a1.x, se * hv.y + a0.y + a1.y);
    *(float2*)(g_x + (size_t)wid * HID + lane * 2) = o;
}

// Fused 3x (Linear 64x64 + ReLU), 3xTF32 split mma, BN stats. Single X buffer
// (each warp owns its 16 rows exclusively -> in-place stage update).
#define MROWS 128
#define XS 76
#define WSTR 72
#define MLP_SMEM ((MROWS * XS + 2 * HID * WSTR + HID + 2 * HID) * 4)

__global__ __launch_bounds__(256, 2)
void k_mlp(const float* __restrict__ Wall, const float* __restrict__ ball, int l) {
    extern __shared__ float sm[];
    float* Xbuf = sm;
    unsigned* Whi = (unsigned*)(sm + MROWS * XS);
    unsigned* Wlo = Whi + HID * WSTR;
    float* Bsm = (float*)(Wlo + HID * WSTR);
    float* bstat = Bsm + HID;

    const int t = threadIdx.x;
    const int warp = t >> 5, lane = t & 31;
    const int g = lane >> 2, tg = lane & 3;
    const int row0 = blockIdx.x * MROWS;
    const int wrow = warp * 16;

    if (t < 2 * HID) bstat[t] = 0.f;

    for (int i = t; i < MROWS * 16; i += 256) {
        int r = i >> 4, q = i & 15;
        float4 v = make_float4(0.f, 0.f, 0.f, 0.f);
        int gr = row0 + r;
        if (gr < NN) v = *(const float4*)(g_x + (size_t)gr * HID + q * 4);
        float* p = Xbuf + r * XS + q * 4;
        p[0] = v.x; p[1] = v.y; p[2] = v.z; p[3] = v.w;
    }

    for (int m = 0; m < 3; m++) {
        __syncthreads();
        const float* W = Wall + (size_t)(l * 3 + m) * HID * HID;
        for (int i = t; i < HID * 16; i += 256) {
            int k = i >> 4, q = i & 15;
            float4 w = *(const float4*)(W + (size_t)k * HID + q * 4);
            unsigned h0 = f2tf(w.x), h1 = f2tf(w.y), h2 = f2tf(w.z), h3 = f2tf(w.w);
            unsigned* ph = Whi + k * WSTR + q * 4;
            ph[0] = h0; ph[1] = h1; ph[2] = h2; ph[3] = h3;
            unsigned* pl = Wlo + k * WSTR + q * 4;
            pl[0] = f2tf(w.x - __uint_as_float(h0));
            pl[1] = f2tf(w.y - __uint_as_float(h1));
            pl[2] = f2tf(w.z - __uint_as_float(h2));
            pl[3] = f2tf(w.w - __uint_as_float(h3));
        }
        if (t < HID) Bsm[t] = ball[(l * 3 + m) * HID + t];
        __syncthreads();

        float acc[8][4];
        #pragma unroll
        for (int n = 0; n < 8; n++) {
            acc[n][0] = 0.f; acc[n][1] = 0.f; acc[n][2] = 0.f; acc[n][3] = 0.f;
        }

        #pragma unroll
        for (int k0 = 0; k0 < 8; k0++) {
            int kk = k0 * 8;
            float a0f = Xbuf[(wrow + g) * XS + kk + tg];
            float a1f = Xbuf[(wrow + g + 8) * XS + kk + tg];
            float a2f = Xbuf[(wrow + g) * XS + kk + tg + 4];
            float a3f = Xbuf[(wrow + g + 8) * XS + kk + tg + 4];
            unsigned a0h = f2tf(a0f), a1h = f2tf(a1f);
            unsigned a2h = f2tf(a2f), a3h = f2tf(a3f);
            unsigned a0l = f2tf(a0f - __uint_as_float(a0h));
            unsigned a1l = f2tf(a1f - __uint_as_float(a1h));
            unsigned a2l = f2tf(a2f - __uint_as_float(a2h));
            unsigned a3l = f2tf(a3f - __uint_as_float(a3h));
            #pragma unroll
            for (int n = 0; n < 8; n++) {
                unsigned b0h = Whi[(kk + tg) * WSTR + n * 8 + g];
                unsigned b1h = Whi[(kk + tg + 4) * WSTR + n * 8 + g];
                unsigned b0l = Wlo[(kk + tg) * WSTR + n * 8 + g];
                unsigned b1l = Wlo[(kk + tg + 4) * WSTR + n * 8 + g];
                mma8(acc[n], a0h, a1h, a2h, a3h, b0l, b1l);
                mma8(acc[n], a0l, a1l, a2l, a3l, b0h, b1h);
                mma8(acc[n], a0h, a1h, a2h, a3h, b0h, b1h);
            }
        }

        if (m < 2) {
            // in-place: this warp exclusively owns rows wrow..wrow+15
            #pragma unroll
            for (int n = 0; n < 8; n++) {
                int c = n * 8 + 2 * tg;
                float b0f = Bsm[c], b1f = Bsm[c + 1];
                float d0 = fmaxf(acc[n][0] + b0f, 0.f);
                float d1 = fmaxf(acc[n][1] + b1f, 0.f);
                float d2 = fmaxf(acc[n][2] + b0f, 0.f);
                float d3 = fmaxf(acc[n][3] + b1f, 0.f);
                float* p0 = Xbuf + (wrow + g) * XS + c;
                p0[0] = d0; p0[1] = d1;
                float* p1 = Xbuf + (wrow + g + 8) * XS + c;
                p1[0] = d2; p1[1] = d3;
            }
            __syncwarp();
        } else {
            int r0v = row0 + wrow + g;
            int r1v = r0v + 8;
            bool v0 = r0v < NN, v1 = r1v < NN;
            #pragma unroll
            for (int n = 0; n < 8; n++) {
                int c = n * 8 + 2 * tg;
                float b0f = Bsm[c], b1f = Bsm[c + 1];
                float d0 = fmaxf(acc[n][0] + b0f, 0.f);
                float d1 = fmaxf(acc[n][1] + b1f, 0.f);
                float d2 = fmaxf(acc[n][2] + b0f, 0.f);
                float d3 = fmaxf(acc[n][3] + b1f, 0.f);
                if (v0) *(float2*)(g_y + (size_t)r0v * HID + c) = make_float2(d0, d1);
                if (v1) *(float2*)(g_y + (size_t)r1v * HID + c) = make_float2(d2, d3);
                float s0 = (v0 ? d0 : 0.f) + (v1 ? d2 : 0.f);
                float s1 = (v0 ? d1 : 0.f) + (v1 ? d3 : 0.f);
                float q0 = (v0 ? d0 * d0 : 0.f) + (v1 ? d2 * d2 : 0.f);
                float q1 = (v0 ? d1 * d1 : 0.f) + (v1 ? d3 * d3 : 0.f);
                #pragma unroll
                for (int off = 4; off < 32; off <<= 1) {
                    s0 += __shfl_xor_sync(0xffffffffu, s0, off);
                    s1 += __shfl_xor_sync(0xffffffffu, s1, off);
                    q0 += __shfl_xor_sync(0xffffffffu, q0, off);
                    q1 += __shfl_xor_sync(0xffffffffu, q1, off);
                }
                if (g == 0) {
                    atomicAdd(&bstat[c], s0);
                    atomicAdd(&bstat[c + 1], s1);
                    atomicAdd(&bstat[HID + c], q0);
                    atomicAdd(&bstat[HID + c + 1], q1);
                }
            }
        }
    }
    __syncthreads();
    if (t < 2 * HID) atomicAdd(&g_stats[l * 2 * HID + t], bstat[t]);
}

// BN apply + per-graph pooling. 256 threads = 4 sub-blocks x 64 channels.
__global__ void k_bnpool(const int* __restrict__ graph_ids,
                         const float* __restrict__ gamma,
                         const float* __restrict__ beta, int l) {
    __shared__ int gid[256];
    int t = threadIdx.x;
    int c = t & 63, sub = t >> 6;
    int base = blockIdx.x * 256;
    int nrow_blk = NN - base; if (nrow_blk > 256) nrow_blk = 256;
    if (t < nrow_blk) gid[t] = graph_ids[base + t];
    __syncthreads();

    float sum = g_stats[l * 2 * HID + c];
    float sq = g_stats[l * 2 * HID + HID + c];
    const float invN = 1.0f / (float)NN;
    float mean = sum * invN;
    float var = sq * invN - mean * mean;
    float inv = rsqrtf(var + 1e-5f);
    float sc = __ldg(&gamma[l * HID + c]) * inv;
    float sh = __ldg(&beta[l * HID + c]) - mean * sc;

    int r0 = sub * 64;
    int nr = nrow_blk - r0; if (nr > 64) nr = 64;
    if (nr <= 0) return;

    float run = 0.f;
    int gcur = gid[r0];
    for (int r = 0; r < nr; r++) {
        int gg = gid[r0 + r];
        if (gg != gcur) {
            atomicAdd(&g_pooled[(size_t)gcur * (3 * HID) + l * HID + c], run);
            run = 0.f;
            gcur = gg;
        }
        size_t off = (size_t)(base + r0 + r) * HID + c;
        float v = g_y[off] * sc + sh;
        if (l < 2) g_h[off] = v;
        run += v;
    }
    atomicAdd(&g_pooled[(size_t)gcur * (3 * HID) + l * HID + c], run);
}

// out[g] = pooled[g] @ W_out + b_out
__global__ void k_out(const float* __restrict__ Wo,
                      const float* __restrict__ bo,
                      float* __restrict__ out) {
    __shared__ float p[3 * HID];
    int gr = blockIdx.x;
    int t = threadIdx.x;
    for (int i = t; i < 3 * HID; i += blockDim.x)
        p[i] = g_pooled[(size_t)gr * (3 * HID) + i];
    __syncthreads();
    if (t < NCLS) {
        float a = __ldg(&bo[t]);
        #pragma unroll 8
        for (int k = 0; k < 3 * HID; k++) a += p[k] * Wo[(size_t)k * NCLS + t];
        out[(size_t)gr * NCLS + t] = a;
    }
}

// ---------------- launch ----------------
extern "C" void kernel_launch(void* const* d_in, const int* in_sizes, int n_in,
                              void* d_out, int out_size) {
    const int* node_ids = (const int*)d_in[0];
    const int* edge_src = (const int*)d_in[1];
    const int* edge_dst = (const int*)d_in[2];
    const int* graph_ids = (const int*)d_in[3];
    const float* emb = (const float*)d_in[4];
    const float* Ws = (const float*)d_in[5];
    const float* bs = (const float*)d_in[6];
    const float* gamma = (const float*)d_in[7];
    const float* beta = (const float*)d_in[8];
    const float* eps = (const float*)d_in[9];
    const float* Wo = (const float*)d_in[10];
    const float* bo = (const float*)d_in[11];
    float* out = (float*)d_out;

    cudaFuncSetAttribute(k_mlp, cudaFuncAttributeMaxDynamicSharedMemorySize,
                         MLP_SMEM);

    k_zero<<<256, 256>>>();
    k_hist<<<(NE + 255) / 256, 256>>>(edge_dst);
    k_gather<<<(NN * 16 + 255) / 256, 256>>>(node_ids, emb);
    k_scan<<<1, 1024>>>();
    k_scatter<<<(NE + 255) / 256, 256>>>(edge_src, edge_dst);

    for (int l = 0; l < 3; l++) {
        k_agg<<<(NN * 32 + 255) / 256, 256>>>(eps, l);
        k_mlp<<<(NN + MROWS - 1) / MROWS, 256, MLP_SMEM>>>(Ws, bs, l);
        k_bnpool<<<(NN + 255) / 256, 256>>>(graph_ids, gamma, beta, l);
    }

    k_out<<<NG, 128>>>(Wo, bo, out);
}

// round 5
// speedup vs baseline: 1.4834x; 1.3939x over previous
#include <cuda_runtime.h>
#include <cuda_bf16.h>

#define NN 100000
#define NE 1600000
#define NG 512
#define HID 64
#define NCLS 100
#define IDOFF 1500

#define SCAN_BS 1024
#define SCAN_NB ((NN + SCAN_BS - 1) / SCAN_BS)   // 98

// ---------------- device scratch ----------------
__device__ float g_h[NN * HID];        // layer input h (post-BN)
__device__ float g_x[NN * HID];        // (1+eps)*h + agg  (MLP input)
__device__ float g_y[NN * HID];        // MLP output (pre-BN)
__device__ float g_stats[3 * 2 * HID];
__device__ float g_pooled[NG * 3 * HID];
// CSR build (per-launch, graph static within launch)
__device__ int g_deg[NN];
__device__ int g_off[NN + 1];
__device__ int g_cur[NN];
__device__ int g_csr[NE];
__device__ int g_bsum[SCAN_NB];   // block totals
__device__ int g_boff[SCAN_NB];   // exclusive block offsets

// ---------------- helpers ----------------
__device__ __forceinline__ unsigned f2tf(float f) {
    unsigned u;
    asm("cvt.rna.tf32.f32 %0, %1;" : "=r"(u) : "f"(f));
    return u;
}

__device__ __forceinline__ void mma8(float c[4], unsigned a0, unsigned a1,
                                     unsigned a2, unsigned a3,
                                     unsigned b0, unsigned b1) {
    asm volatile(
        "mma.sync.aligned.m16n8k8.row.col.f32.tf32.tf32.f32 "
        "{%0,%1,%2,%3}, {%4,%5,%6,%7}, {%8,%9}, {%0,%1,%2,%3};\n"
        : "+f"(c[0]), "+f"(c[1]), "+f"(c[2]), "+f"(c[3])
        : "r"(a0), "r"(a1), "r"(a2), "r"(a3), "r"(b0), "r"(b1));
}

// ---------------- kernels ----------------

__global__ void k_zero() {
    int t = blockIdx.x * blockDim.x + threadIdx.x;
    int stride = gridDim.x * blockDim.x;
    for (int i = t; i < NG * 3 * HID; i += stride) g_pooled[i] = 0.f;
    for (int i = t; i < 3 * 2 * HID; i += stride) g_stats[i] = 0.f;
    for (int i = t; i < NN; i += stride) g_deg[i] = 0;
}

__global__ void k_hist(const int* __restrict__ dst) {
    int e = blockIdx.x * blockDim.x + threadIdx.x;
    if (e < NE) atomicAdd(&g_deg[__ldg(&dst[e])], 1);
}

// phase 1: per-block exclusive scan (1024 elems/block) + block totals
__global__ void k_scan1() {
    __shared__ int s[SCAN_BS];
    int t = threadIdx.x;
    int i = blockIdx.x * SCAN_BS + t;
    int v = (i < NN) ? g_deg[i] : 0;
    s[t] = v;
    __syncthreads();
    #pragma unroll
    for (int off = 1; off < SCAN_BS; off <<= 1) {
        int u = (t >= off) ? s[t - off] : 0;
        __syncthreads();
        s[t] += u;
        __syncthreads();
    }
    if (i < NN) g_off[i] = s[t] - v;   // exclusive, block-local
    if (t == SCAN_BS - 1) g_bsum[blockIdx.x] = s[t];
}

// phase 2: scan the block totals (98 values) in one small block
__global__ void k_scan2() {
    __shared__ int s[128];
    int t = threadIdx.x;
    int v = (t < SCAN_NB) ? g_bsum[t] : 0;
    s[t] = v;
    __syncthreads();
    #pragma unroll
    for (int off = 1; off < 128; off <<= 1) {
        int u = (t >= off) ? s[t - off] : 0;
        __syncthreads();
        s[t] += u;
        __syncthreads();
    }
    if (t < SCAN_NB) g_boff[t] = s[t] - v;   // exclusive
    if (t == 127) g_off[NN] = s[127];        // total == NE
}

// phase 3: add block offsets, init g_cur
__global__ void k_scan3() {
    int i = blockIdx.x * SCAN_BS + threadIdx.x;
    if (i >= NN) return;
    int o = g_off[i] + g_boff[blockIdx.x];
    g_off[i] = o;
    g_cur[i] = o;
}

__global__ void k_scatter(const int* __restrict__ src,
                          const int* __restrict__ dst) {
    int e = blockIdx.x * blockDim.x + threadIdx.x;
    if (e >= NE) return;
    int d = __ldg(&dst[e]);
    int pos = atomicAdd(&g_cur[d], 1);
    g_csr[pos] = __ldg(&src[e]);
}

// h = emb[node_ids + IDOFF]
__global__ void k_gather(const int* __restrict__ ids,
                         const float* __restrict__ emb) {
    int t = blockIdx.x * blockDim.x + threadIdx.x;
    if (t >= NN * 16) return;
    int row = t >> 4, q = t & 15;
    int id = ids[row] + IDOFF;
    float4 v = *(const float4*)(emb + (size_t)id * HID + q * 4);
    *(float4*)(g_h + (size_t)row * HID + q * 4) = v;
}

// x[n] = (1+eps[l]) * h[n] + sum_{s in in-nbrs(n)} h[s]   (warp per node)
__global__ __launch_bounds__(256)
void k_agg(const float* __restrict__ eps, int l) {
    int wid = (blockIdx.x * blockDim.x + threadIdx.x) >> 5;
    if (wid >= NN) return;
    int lane = threadIdx.x & 31;
    int beg = __ldg(&g_off[wid]);
    int end = __ldg(&g_off[wid + 1]);
    float2 a0 = make_float2(0.f, 0.f);
    float2 a1 = make_float2(0.f, 0.f);
    int j = beg;
    for (; j + 1 < end; j += 2) {
        int s0 = __ldg(&g_csr[j]);
        int s1 = __ldg(&g_csr[j + 1]);
        float2 v0 = __ldg((const float2*)(g_h + (size_t)s0 * HID + lane * 2));
        float2 v1 = __ldg((const float2*)(g_h + (size_t)s1 * HID + lane * 2));
        a0.x += v0.x; a0.y += v0.y;
        a1.x += v1.x; a1.y += v1.y;
    }
    if (j < end) {
        int s0 = __ldg(&g_csr[j]);
        float2 v0 = __ldg((const float2*)(g_h + (size_t)s0 * HID + lane * 2));
        a0.x += v0.x; a0.y += v0.y;
    }
    float se = 1.0f + __ldg(&eps[l]);
    float2 hv = *(const float2*)(g_h + (size_t)wid * HID + lane * 2);
    float2 o = make_float2(se * hv.x + a0.x + a1.x, se * hv.y + a0.y + a1.y);
    *(float2*)(g_x + (size_t)wid * HID + lane * 2) = o;
}

// Fused 3x (Linear 64x64 + ReLU), 3xTF32 split mma, BN stats. Single X buffer.
#define MROWS 128
#define XS 76
#define WSTR 72
#define MLP_SMEM ((MROWS * XS + 2 * HID * WSTR + HID + 2 * HID) * 4)

__global__ __launch_bounds__(256, 2)
void k_mlp(const float* __restrict__ Wall, const float* __restrict__ ball, int l) {
    extern __shared__ float sm[];
    float* Xbuf = sm;
    unsigned* Whi = (unsigned*)(sm + MROWS * XS);
    unsigned* Wlo = Whi + HID * WSTR;
    float* Bsm = (float*)(Wlo + HID * WSTR);
    float* bstat = Bsm + HID;

    const int t = threadIdx.x;
    const int warp = t >> 5, lane = t & 31;
    const int g = lane >> 2, tg = lane & 3;
    const int row0 = blockIdx.x * MROWS;
    const int wrow = warp * 16;

    if (t < 2 * HID) bstat[t] = 0.f;

    for (int i = t; i < MROWS * 16; i += 256) {
        int r = i >> 4, q = i & 15;
        float4 v = make_float4(0.f, 0.f, 0.f, 0.f);
        int gr = row0 + r;
        if (gr < NN) v = *(const float4*)(g_x + (size_t)gr * HID + q * 4);
        float* p = Xbuf + r * XS + q * 4;
        p[0] = v.x; p[1] = v.y; p[2] = v.z; p[3] = v.w;
    }

    for (int m = 0; m < 3; m++) {
        __syncthreads();
        const float* W = Wall + (size_t)(l * 3 + m) * HID * HID;
        for (int i = t; i < HID * 16; i += 256) {
            int k = i >> 4, q = i & 15;
            float4 w = *(const float4*)(W + (size_t)k * HID + q * 4);
            unsigned h0 = f2tf(w.x), h1 = f2tf(w.y), h2 = f2tf(w.z), h3 = f2tf(w.w);
            unsigned* ph = Whi + k * WSTR + q * 4;
            ph[0] = h0; ph[1] = h1; ph[2] = h2; ph[3] = h3;
            unsigned* pl = Wlo + k * WSTR + q * 4;
            pl[0] = f2tf(w.x - __uint_as_float(h0));
            pl[1] = f2tf(w.y - __uint_as_float(h1));
            pl[2] = f2tf(w.z - __uint_as_float(h2));
            pl[3] = f2tf(w.w - __uint_as_float(h3));
        }
        if (t < HID) Bsm[t] = ball[(l * 3 + m) * HID + t];
        __syncthreads();

        float acc[8][4];
        #pragma unroll
        for (int n = 0; n < 8; n++) {
            acc[n][0] = 0.f; acc[n][1] = 0.f; acc[n][2] = 0.f; acc[n][3] = 0.f;
        }

        #pragma unroll
        for (int k0 = 0; k0 < 8; k0++) {
            int kk = k0 * 8;
            float a0f = Xbuf[(wrow + g) * XS + kk + tg];
            float a1f = Xbuf[(wrow + g + 8) * XS + kk + tg];
            float a2f = Xbuf[(wrow + g) * XS + kk + tg + 4];
            float a3f = Xbuf[(wrow + g + 8) * XS + kk + tg + 4];
            unsigned a0h = f2tf(a0f), a1h = f2tf(a1f);
            unsigned a2h = f2tf(a2f), a3h = f2tf(a3f);
            unsigned a0l = f2tf(a0f - __uint_as_float(a0h));
            unsigned a1l = f2tf(a1f - __uint_as_float(a1h));
            unsigned a2l = f2tf(a2f - __uint_as_float(a2h));
            unsigned a3l = f2tf(a3f - __uint_as_float(a3h));
            #pragma unroll
            for (int n = 0; n < 8; n++) {
                unsigned b0h = Whi[(kk + tg) * WSTR + n * 8 + g];
                unsigned b1h = Whi[(kk + tg + 4) * WSTR + n * 8 + g];
                unsigned b0l = Wlo[(kk + tg) * WSTR + n * 8 + g];
                unsigned b1l = Wlo[(kk + tg + 4) * WSTR + n * 8 + g];
                mma8(acc[n], a0h, a1h, a2h, a3h, b0l, b1l);
                mma8(acc[n], a0l, a1l, a2l, a3l, b0h, b1h);
                mma8(acc[n], a0h, a1h, a2h, a3h, b0h, b1h);
            }
        }

        if (m < 2) {
            #pragma unroll
            for (int n = 0; n < 8; n++) {
                int c = n * 8 + 2 * tg;
                float b0f = Bsm[c], b1f = Bsm[c + 1];
                float d0 = fmaxf(acc[n][0] + b0f, 0.f);
                float d1 = fmaxf(acc[n][1] + b1f, 0.f);
                float d2 = fmaxf(acc[n][2] + b0f, 0.f);
                float d3 = fmaxf(acc[n][3] + b1f, 0.f);
                float* p0 = Xbuf + (wrow + g) * XS + c;
                p0[0] = d0; p0[1] = d1;
                float* p1 = Xbuf + (wrow + g + 8) * XS + c;
                p1[0] = d2; p1[1] = d3;
            }
            __syncwarp();
        } else {
            int r0v = row0 + wrow + g;
            int r1v = r0v + 8;
            bool v0 = r0v < NN, v1 = r1v < NN;
            #pragma unroll
            for (int n = 0; n < 8; n++) {
                int c = n * 8 + 2 * tg;
                float b0f = Bsm[c], b1f = Bsm[c + 1];
                float d0 = fmaxf(acc[n][0] + b0f, 0.f);
                float d1 = fmaxf(acc[n][1] + b1f, 0.f);
                float d2 = fmaxf(acc[n][2] + b0f, 0.f);
                float d3 = fmaxf(acc[n][3] + b1f, 0.f);
                if (v0) *(float2*)(g_y + (size_t)r0v * HID + c) = make_float2(d0, d1);
                if (v1) *(float2*)(g_y + (size_t)r1v * HID + c) = make_float2(d2, d3);
                float s0 = (v0 ? d0 : 0.f) + (v1 ? d2 : 0.f);
                float s1 = (v0 ? d1 : 0.f) + (v1 ? d3 : 0.f);
                float q0 = (v0 ? d0 * d0 : 0.f) + (v1 ? d2 * d2 : 0.f);
                float q1 = (v0 ? d1 * d1 : 0.f) + (v1 ? d3 * d3 : 0.f);
                #pragma unroll
                for (int off = 4; off < 32; off <<= 1) {
                    s0 += __shfl_xor_sync(0xffffffffu, s0, off);
                    s1 += __shfl_xor_sync(0xffffffffu, s1, off);
                    q0 += __shfl_xor_sync(0xffffffffu, q0, off);
                    q1 += __shfl_xor_sync(0xffffffffu, q1, off);
                }
                if (g == 0) {
                    atomicAdd(&bstat[c], s0);
                    atomicAdd(&bstat[c + 1], s1);
                    atomicAdd(&bstat[HID + c], q0);
                    atomicAdd(&bstat[HID + c + 1], q1);
                }
            }
        }
    }
    __syncthreads();
    if (t < 2 * HID) atomicAdd(&g_stats[l * 2 * HID + t], bstat[t]);
}

// BN apply + per-graph pooling. 256 threads = 4 sub-blocks x 64 channels.
__global__ void k_bnpool(const int* __restrict__ graph_ids,
                         const float* __restrict__ gamma,
                         const float* __restrict__ beta, int l) {
    __shared__ int gid[256];
    int t = threadIdx.x;
    int c = t & 63, sub = t >> 6;
    int base = blockIdx.x * 256;
    int nrow_blk = NN - base; if (nrow_blk > 256) nrow_blk = 256;
    if (t < nrow_blk) gid[t] = graph_ids[base + t];
    __syncthreads();

    float sum = g_stats[l * 2 * HID + c];
    float sq = g_stats[l * 2 * HID + HID + c];
    const float invN = 1.0f / (float)NN;
    float mean = sum * invN;
    float var = sq * invN - mean * mean;
    float inv = rsqrtf(var + 1e-5f);
    float sc = __ldg(&gamma[l * HID + c]) * inv;
    float sh = __ldg(&beta[l * HID + c]) - mean * sc;

    int r0 = sub * 64;
    int nr = nrow_blk - r0; if (nr > 64) nr = 64;
    if (nr <= 0) return;

    float run = 0.f;
    int gcur = gid[r0];
    for (int r = 0; r < nr; r++) {
        int gg = gid[r0 + r];
        if (gg != gcur) {
            atomicAdd(&g_pooled[(size_t)gcur * (3 * HID) + l * HID + c], run);
            run = 0.f;
            gcur = gg;
        }
        size_t off = (size_t)(base + r0 + r) * HID + c;
        float v = g_y[off] * sc + sh;
        if (l < 2) g_h[off] = v;
        run += v;
    }
    atomicAdd(&g_pooled[(size_t)gcur * (3 * HID) + l * HID + c], run);
}

// out[g] = pooled[g] @ W_out + b_out
__global__ void k_out(const float* __restrict__ Wo,
                      const float* __restrict__ bo,
                      float* __restrict__ out) {
    __shared__ float p[3 * HID];
    int gr = blockIdx.x;
    int t = threadIdx.x;
    for (int i = t; i < 3 * HID; i += blockDim.x)
        p[i] = g_pooled[(size_t)gr * (3 * HID) + i];
    __syncthreads();
    if (t < NCLS) {
        float a = __ldg(&bo[t]);
        #pragma unroll 8
        for (int k = 0; k < 3 * HID; k++) a += p[k] * Wo[(size_t)k * NCLS + t];
        out[(size_t)gr * NCLS + t] = a;
    }
}

// ---------------- launch ----------------
extern "C" void kernel_launch(void* const* d_in, const int* in_sizes, int n_in,
                              void* d_out, int out_size) {
    const int* node_ids = (const int*)d_in[0];
    const int* edge_src = (const int*)d_in[1];
    const int* edge_dst = (const int*)d_in[2];
    const int* graph_ids = (const int*)d_in[3];
    const float* emb = (const float*)d_in[4];
    const float* Ws = (const float*)d_in[5];
    const float* bs = (const float*)d_in[6];
    const float* gamma = (const float*)d_in[7];
    const float* beta = (const float*)d_in[8];
    const float* eps = (const float*)d_in[9];
    const float* Wo = (const float*)d_in[10];
    const float* bo = (const float*)d_in[11];
    float* out = (float*)d_out;

    cudaFuncSetAttribute(k_mlp, cudaFuncAttributeMaxDynamicSharedMemorySize,
                         MLP_SMEM);

    k_zero<<<256, 256>>>();
    k_hist<<<(NE + 255) / 256, 256>>>(edge_dst);
    k_gather<<<(NN * 16 + 255) / 256, 256>>>(node_ids, emb);
    k_scan1<<<SCAN_NB, SCAN_BS>>>();
    k_scan2<<<1, 128>>>();
    k_scan3<<<SCAN_NB, SCAN_BS>>>();
    k_scatter<<<(NE + 255) / 256, 256>>>(edge_src, edge_dst);

    for (int l = 0; l < 3; l++) {
        k_agg<<<(NN * 32 + 255) / 256, 256>>>(eps, l);
        k_mlp<<<(NN + MROWS - 1) / MROWS, 256, MLP_SMEM>>>(Ws, bs, l);
        k_bnpool<<<(NN + 255) / 256, 256>>>(graph_ids, gamma, beta, l);
    }

    k_out<<<NG, 128>>>(Wo, bo, out);
}